// round 15
// baseline (speedup 1.0000x reference)
#include <cuda_runtime.h>
#include <cuda_bf16.h>
#include <stdint.h>
#include <math.h>

#define EPSF 1e-8f
#define NMAX 50000
#define D1 128
#define D2 256

typedef unsigned long long u64;

// ---------------------------------------------------------------------------
// Scratch (device globals — no allocation allowed).
// ---------------------------------------------------------------------------
__device__ float4 g_agg1_[(size_t)NMAX * D1 / 4];
__device__ float4 g_h_[(size_t)NMAX * D2 / 4];
__device__ float4 g_agg2_[(size_t)NMAX * D2 / 4];
__device__ uint4  g_xq_[(size_t)NMAX * D1 / 16];   // int8 x/||x|| * 127
__device__ uint4  g_hq_[(size_t)NMAX * D2 / 16];   // int8 h/||h|| * 127
__device__ float  g_xnorm[NMAX];
__device__ float  g_hnorm[NMAX];
__device__ float  g_xa[NMAX];                      // sum|q|/127 for x
__device__ float  g_ha[NMAX];                      // sum|q|/127 for h
__device__ int    g_is64;

// ---------------------------------------------------------------------------
// helpers
// ---------------------------------------------------------------------------
__device__ __forceinline__ int dp4a(int a, int b, int c) {
    int d;
    asm("dp4a.s32.s32 %0, %1, %2, %3;" : "=r"(d) : "r"(a), "r"(b), "r"(c));
    return d;
}
// quantize 4 floats (pre-scaled by s127) -> packed int8x4; accumulate |q|
__device__ __forceinline__ unsigned q4pack(float4 v, float s127, int& asum) {
    int a0 = __float2int_rn(v.x * s127);
    int a1 = __float2int_rn(v.y * s127);
    int a2 = __float2int_rn(v.z * s127);
    int a3 = __float2int_rn(v.w * s127);
    asum += abs(a0) + abs(a1) + abs(a2) + abs(a3);
    return (unsigned)(a0 & 0xFF) | ((unsigned)(a1 & 0xFF) << 8) |
           ((unsigned)(a2 & 0xFF) << 16) | ((unsigned)(a3 & 0xFF) << 24);
}
// packed f32x2 FMA (B300 FFMA2)
__device__ __forceinline__ u64 dup2(float a) {
    u64 r;
    asm("mov.b64 %0, {%1, %1};" : "=l"(r) : "f"(a));
    return r;
}
__device__ __forceinline__ u64 fma2(u64 a, u64 b, u64 c) {
    u64 d;
    asm("fma.rn.f32x2 %0, %1, %2, %3;" : "=l"(d) : "l"(a), "l"(b), "l"(c));
    return d;
}
__device__ __forceinline__ float2 unpk(u64 a) {
    float2 f;
    asm("mov.b64 {%0, %1}, %2;" : "=f"(f.x), "=f"(f.y) : "l"(a));
    return f;
}

// ---------------------------------------------------------------------------
// setup kernels
// ---------------------------------------------------------------------------
__global__ void k_reset_flag() { g_is64 = 1; }

__global__ void k_detect64(const void* __restrict__ eidx, int E, int N) {
    int i = blockIdx.x * blockDim.x + threadIdx.x;
    if (i < E) {
        long long v = ((const long long*)eidx)[i];
        if (v < 0 || v >= (long long)N) g_is64 = 0;
    }
}

// ---------------------------------------------------------------------------
// Per-node norms + self-loop init + int8 quantization of x/||x|| (layer 1).
// ---------------------------------------------------------------------------
__global__ void k_norms_init128(const float* __restrict__ feat,
                                float* __restrict__ norms,
                                float* __restrict__ absums,
                                float* __restrict__ agg,
                                unsigned* __restrict__ fq, int N)
{
    int node = (blockIdx.x * blockDim.x + threadIdx.x) >> 5;
    int lane = threadIdx.x & 31;
    if (node >= N) return;
    const float4* f = (const float4*)(feat + (size_t)node * D1);
    float4* a = (float4*)(agg + (size_t)node * D1);
    float4 v = f[lane];
    float n2 = v.x * v.x + v.y * v.y + v.z * v.z + v.w * v.w;
#pragma unroll
    for (int o = 16; o; o >>= 1) n2 += __shfl_xor_sync(0xffffffffu, n2, o);
    float nrm = sqrtf(n2);
    if (lane == 0) norms[node] = nrm;
    float s127 = (nrm > 0.f) ? 127.f / nrm : 0.f;
    int asum = 0;
    fq[(size_t)node * 32 + lane] = q4pack(v, s127, asum);
#pragma unroll
    for (int o = 16; o; o >>= 1) asum += __shfl_xor_sync(0xffffffffu, asum, o);
    if (lane == 0) absums[node] = (float)asum * (1.f / 127.f);
    float denom = fmaxf(nrm * nrm, EPSF);
    bool pass = n2 > 0.5f * denom;
    float4 z = make_float4(0.f, 0.f, 0.f, 0.f);
    a[lane] = pass ? v : z;
}

// ---------------------------------------------------------------------------
// Edge pass, quarter-warp per edge, int8 DP4A dot with per-edge exact margin.
// ---------------------------------------------------------------------------
template<int D>
__global__ void k_edge_i8(const float* __restrict__ feat,
                          const uint4* __restrict__ fq,
                          const float* __restrict__ norms,
                          const float* __restrict__ absums,
                          const void* __restrict__ eidx,
                          float* __restrict__ agg, int E)
{
    constexpr int NSTRIDE = D / 16;   // uint4 per int8 row
    constexpr int NU = D / 128;       // uint4 per lane per endpoint
    long long wid = (long long)((blockIdx.x * (unsigned)blockDim.x + threadIdx.x) >> 5);
    if (wid * 4 >= E) return;
    int lane = threadIdx.x & 31;
    int sl = lane & 7;
    long long e = wid * 4 + (lane >> 3);
    bool valid = (e < E);
    long long ec = valid ? e : (long long)E - 1;

    int s, d;
    if (g_is64) {
        const long long* p = (const long long*)eidx;
        s = (int)p[ec];
        d = (int)p[ec + E];
    } else {
        const int* p = (const int*)eidx;
        s = p[ec];
        d = p[ec + E];
    }
    // absums: independent of features, issues in parallel
    float SA = absums[s];
    float SB = absums[d];

    const uint4* ps = fq + (size_t)s * NSTRIDE;
    const uint4* pd = fq + (size_t)d * NSTRIDE;
    uint4 a[NU], b[NU];
#pragma unroll
    for (int i = 0; i < NU; i++) {
        a[i] = ps[sl + 8 * i];
        b[i] = pd[sl + 8 * i];
    }

    int dot = 0;
#pragma unroll
    for (int i = 0; i < NU; i++) {
        dot = dp4a((int)a[i].x, (int)b[i].x, dot);
        dot = dp4a((int)a[i].y, (int)b[i].y, dot);
        dot = dp4a((int)a[i].z, (int)b[i].z, dot);
        dot = dp4a((int)a[i].w, (int)b[i].w, dot);
    }
#pragma unroll
    for (int o = 1; o < 8; o <<= 1) dot += __shfl_xor_sync(0xffffffffu, dot, o);

    float t = (float)dot * (1.f / 16129.f);
    // |t - sim| <= (SA + SB + D/254)/254  (+ fp pad)
    float margin = (SA + SB + (float)D * (1.f / 254.f)) * (1.f / 254.f) + 1e-4f;

    bool pass;
    if (fabsf(t - 0.5f) > margin) {
        pass = (t > 0.5f);
    } else {
        // rescue: exact fp32 reference comparison (rare; group-uniform branch)
        unsigned hm = 0xFFu << (lane & 24);
        float nn = norms[s] * norms[d];
        const float4* fs = (const float4*)(feat + (size_t)s * D);
        const float4* fd = (const float4*)(feat + (size_t)d * D);
        float ex = 0.f;
#pragma unroll
        for (int i = 0; i < D / 32; i++) {
            float4 av = fs[sl + 8 * i];
            float4 bv = fd[sl + 8 * i];
            ex += av.x * bv.x + av.y * bv.y + av.z * bv.z + av.w * bv.w;
        }
#pragma unroll
        for (int o = 1; o < 8; o <<= 1) ex += __shfl_xor_sync(hm, ex, o);
        pass = (ex > 0.5f * fmaxf(nn, EPSF));
    }

    if (valid && pass) {
        const float4* fs = (const float4*)(feat + (size_t)s * D);
        float* out = agg + (size_t)d * D;
#pragma unroll
        for (int i = 0; i < D / 32; i++) {
            float4 av = fs[sl + 8 * i];
            asm volatile("red.global.add.v4.f32 [%0], {%1,%2,%3,%4};" ::
                         "l"(out + (sl + 8 * i) * 4),
                         "f"(av.x), "f"(av.y), "f"(av.z), "f"(av.w)
                         : "memory");
        }
    }
}

// ---------------------------------------------------------------------------
// GEMM1 (f32x2 + prefetch): h = relu(agg1 @ W1^T + b1). Block 64x256, K=128.
// Fused epilogue: h (fp32), h int8 (normalized), hnorm, h absum, agg2 init.
// ---------------------------------------------------------------------------
__global__ __launch_bounds__(256)
void k_gemm1_f2(const float* __restrict__ A, const float* __restrict__ W,
                const float* __restrict__ bias,
                float* __restrict__ hq, unsigned short* __restrict__ hqi,
                float* __restrict__ hnq, float* __restrict__ haq,
                float* __restrict__ aggq, int M)
{
    __shared__ float As[16][64];
    __shared__ float Ws[16][256];
    int tid = threadIdx.x;
    int tx = tid & 31;
    int ty = tid >> 5;
    int m0 = blockIdx.x * 64;

    int lm = tid >> 2, lkq = tid & 3;
    int lgm = m0 + lm;
    if (lgm >= M) lgm = M - 1;
    const float* Arow = A + (size_t)lgm * 128 + lkq * 4;
    const float* Wbase = W + (size_t)lm * 128 + lkq * 4;

    u64 acc[8][4];
#pragma unroll
    for (int i = 0; i < 8; i++)
#pragma unroll
        for (int j = 0; j < 4; j++) acc[i][j] = 0ull;

    float4 va = *(const float4*)Arow;
    float4 vw[4];
#pragma unroll
    for (int j = 0; j < 4; j++)
        vw[j] = *(const float4*)(Wbase + (size_t)j * 64 * 128);

    for (int k0 = 0; k0 < 128; k0 += 16) {
        As[lkq * 4 + 0][lm] = va.x;
        As[lkq * 4 + 1][lm] = va.y;
        As[lkq * 4 + 2][lm] = va.z;
        As[lkq * 4 + 3][lm] = va.w;
#pragma unroll
        for (int j = 0; j < 4; j++) {
            int n = lm + 64 * j;
            Ws[lkq * 4 + 0][n] = vw[j].x;
            Ws[lkq * 4 + 1][n] = vw[j].y;
            Ws[lkq * 4 + 2][n] = vw[j].z;
            Ws[lkq * 4 + 3][n] = vw[j].w;
        }
        __syncthreads();
        if (k0 + 16 < 128) {
            va = *(const float4*)(Arow + k0 + 16);
#pragma unroll
            for (int j = 0; j < 4; j++)
                vw[j] = *(const float4*)(Wbase + (size_t)j * 64 * 128 + k0 + 16);
        }
#pragma unroll
        for (int k = 0; k < 16; k++) {
            u64 rm2[8], rn[4];
#pragma unroll
            for (int i = 0; i < 8; i++) rm2[i] = dup2(As[k][ty * 8 + i]);
#pragma unroll
            for (int j = 0; j < 4; j++)
                rn[j] = *(const u64*)&Ws[k][2 * tx + 64 * j];
#pragma unroll
            for (int i = 0; i < 8; i++)
#pragma unroll
                for (int j = 0; j < 4; j++)
                    acc[i][j] = fma2(rm2[i], rn[j], acc[i][j]);
        }
        __syncthreads();
    }

    float2 bb[4];
#pragma unroll
    for (int j = 0; j < 4; j++) bb[j] = *(const float2*)&bias[2 * tx + 64 * j];

#pragma unroll
    for (int i = 0; i < 8; i++) {
        int gm = m0 + ty * 8 + i;
        float v[8];
        float n2 = 0.f;
#pragma unroll
        for (int j = 0; j < 4; j++) {
            float2 t = unpk(acc[i][j]);
            float v0 = fmaxf(t.x + bb[j].x, 0.f);
            float v1 = fmaxf(t.y + bb[j].y, 0.f);
            v[2 * j] = v0;
            v[2 * j + 1] = v1;
            n2 += v0 * v0 + v1 * v1;
        }
#pragma unroll
        for (int o = 16; o; o >>= 1) n2 += __shfl_xor_sync(0xffffffffu, n2, o);
        bool pass = n2 > 0.5f * fmaxf(n2, EPSF);
        float nrm = sqrtf(n2);
        float s127 = (nrm > 0.f) ? 127.f / nrm : 0.f;
        int asum = 0;
        unsigned short qp[4];
#pragma unroll
        for (int j = 0; j < 4; j++) {
            int q0 = __float2int_rn(v[2 * j] * s127);
            int q1 = __float2int_rn(v[2 * j + 1] * s127);
            asum += q0 + q1;   // relu'd -> nonnegative
            qp[j] = (unsigned short)((q0 & 0xFF) | ((q1 & 0xFF) << 8));
        }
#pragma unroll
        for (int o = 16; o; o >>= 1) asum += __shfl_xor_sync(0xffffffffu, asum, o);
        if (gm < M) {
            if (tx == 0) {
                hnq[gm] = nrm;
                haq[gm] = (float)asum * (1.f / 127.f);
            }
            float2 z2 = make_float2(0.f, 0.f);
#pragma unroll
            for (int j = 0; j < 4; j++) {
                float2 hv = make_float2(v[2 * j], v[2 * j + 1]);
                *(float2*)(hq + (size_t)gm * 256 + 2 * tx + 64 * j) = hv;
                *(float2*)(aggq + (size_t)gm * 256 + 2 * tx + 64 * j) = pass ? hv : z2;
                hqi[(size_t)gm * 128 + tx + 32 * j] = qp[j];
            }
        }
    }
}

// ---------------------------------------------------------------------------
// GEMM2 (f32x2 + prefetch): out = log_softmax(agg2 @ W2^T + b2). 128x64, K=256.
// ---------------------------------------------------------------------------
__global__ __launch_bounds__(256)
void k_gemm2_f2(const float* __restrict__ A, const float* __restrict__ W,
                const float* __restrict__ bias,
                float* __restrict__ outq, int M)
{
    __shared__ float As[16][128];
    __shared__ float Ws[16][64];
    int tid = threadIdx.x;
    int tx = tid & 15;
    int ty = tid >> 4;
    int m0 = blockIdx.x * 128;

    int lm = tid >> 2, lkq = tid & 3;
    int lgm0 = m0 + lm;
    if (lgm0 >= M) lgm0 = M - 1;
    int lgm1 = m0 + lm + 64;
    if (lgm1 >= M) lgm1 = M - 1;
    const float* Arow0 = A + (size_t)lgm0 * 256 + lkq * 4;
    const float* Arow1 = A + (size_t)lgm1 * 256 + lkq * 4;
    const float* Wrow = W + (size_t)lm * 256 + lkq * 4;

    u64 acc[8][2];
#pragma unroll
    for (int i = 0; i < 8; i++) {
        acc[i][0] = 0ull;
        acc[i][1] = 0ull;
    }

    float4 va0 = *(const float4*)Arow0;
    float4 va1 = *(const float4*)Arow1;
    float4 vw = *(const float4*)Wrow;

    for (int k0 = 0; k0 < 256; k0 += 16) {
        As[lkq * 4 + 0][lm] = va0.x;
        As[lkq * 4 + 1][lm] = va0.y;
        As[lkq * 4 + 2][lm] = va0.z;
        As[lkq * 4 + 3][lm] = va0.w;
        As[lkq * 4 + 0][lm + 64] = va1.x;
        As[lkq * 4 + 1][lm + 64] = va1.y;
        As[lkq * 4 + 2][lm + 64] = va1.z;
        As[lkq * 4 + 3][lm + 64] = va1.w;
        Ws[lkq * 4 + 0][lm] = vw.x;
        Ws[lkq * 4 + 1][lm] = vw.y;
        Ws[lkq * 4 + 2][lm] = vw.z;
        Ws[lkq * 4 + 3][lm] = vw.w;
        __syncthreads();
        if (k0 + 16 < 256) {
            va0 = *(const float4*)(Arow0 + k0 + 16);
            va1 = *(const float4*)(Arow1 + k0 + 16);
            vw = *(const float4*)(Wrow + k0 + 16);
        }
#pragma unroll
        for (int k = 0; k < 16; k++) {
            u64 rm2[8], rn[2];
#pragma unroll
            for (int i = 0; i < 8; i++) rm2[i] = dup2(As[k][ty * 8 + i]);
            rn[0] = *(const u64*)&Ws[k][2 * tx];
            rn[1] = *(const u64*)&Ws[k][2 * tx + 32];
#pragma unroll
            for (int i = 0; i < 8; i++) {
                acc[i][0] = fma2(rm2[i], rn[0], acc[i][0]);
                acc[i][1] = fma2(rm2[i], rn[1], acc[i][1]);
            }
        }
        __syncthreads();
    }

    float2 bb0 = *(const float2*)&bias[2 * tx];
    float2 bb1 = *(const float2*)&bias[2 * tx + 32];

#pragma unroll
    for (int i = 0; i < 8; i++) {
        int gm = m0 + ty * 8 + i;
        float2 t0 = unpk(acc[i][0]);
        float2 t1 = unpk(acc[i][1]);
        float v0 = t0.x + bb0.x, v1 = t0.y + bb0.y;
        float v2 = t1.x + bb1.x, v3 = t1.y + bb1.y;
        float mx = fmaxf(fmaxf(v0, v1), fmaxf(v2, v3));
#pragma unroll
        for (int o = 1; o < 16; o <<= 1)
            mx = fmaxf(mx, __shfl_xor_sync(0xffffffffu, mx, o));
        float sm = __expf(v0 - mx) + __expf(v1 - mx) +
                   __expf(v2 - mx) + __expf(v3 - mx);
#pragma unroll
        for (int o = 1; o < 16; o <<= 1)
            sm += __shfl_xor_sync(0xffffffffu, sm, o);
        float l = mx + __logf(sm);
        if (gm < M) {
            *(float2*)(outq + (size_t)gm * 64 + 2 * tx) = make_float2(v0 - l, v1 - l);
            *(float2*)(outq + (size_t)gm * 64 + 2 * tx + 32) = make_float2(v2 - l, v3 - l);
        }
    }
}

// ---------------------------------------------------------------------------
extern "C" void kernel_launch(void* const* d_in, const int* in_sizes, int n_in,
                              void* d_out, int out_size)
{
    const float* x   = (const float*)d_in[0];
    const void*  eix = d_in[1];
    const float* W1  = (const float*)d_in[2];
    const float* b1  = (const float*)d_in[3];
    const float* W2  = (const float*)d_in[4];
    const float* b2  = (const float*)d_in[5];
    float* out = (float*)d_out;

    int N = in_sizes[0] / D1;      // 50000
    int E = in_sizes[1] / 2;       // 800000
    (void)n_in; (void)out_size;

    float *agg1, *h, *agg2, *xn, *hn, *xa, *ha;
    uint4 *xq, *hq8;
    cudaGetSymbolAddress((void**)&agg1, g_agg1_);
    cudaGetSymbolAddress((void**)&h,    g_h_);
    cudaGetSymbolAddress((void**)&agg2, g_agg2_);
    cudaGetSymbolAddress((void**)&xq,   g_xq_);
    cudaGetSymbolAddress((void**)&hq8,  g_hq_);
    cudaGetSymbolAddress((void**)&xn,   g_xnorm);
    cudaGetSymbolAddress((void**)&hn,   g_hnorm);
    cudaGetSymbolAddress((void**)&xa,   g_xa);
    cudaGetSymbolAddress((void**)&ha,   g_ha);

    k_reset_flag<<<1, 1>>>();
    k_detect64<<<(E + 255) / 256, 256>>>(eix, E, N);

    int nodeBlocks = (N * 32 + 255) / 256;
    long long warps4 = ((long long)E + 3) / 4;
    int edgeBlocks = (int)((warps4 * 32 + 255) / 256);

    // ---- Layer 1 ----
    k_norms_init128<<<nodeBlocks, 256>>>(x, xn, xa, agg1, (unsigned*)xq, N);
    k_edge_i8<D1><<<edgeBlocks, 256>>>(x, xq, xn, xa, eix, agg1, E);
    k_gemm1_f2<<<(N + 63) / 64, 256>>>(agg1, W1, b1, h, (unsigned short*)hq8, hn, ha, agg2, N);

    // ---- Layer 2 ----
    k_edge_i8<D2><<<edgeBlocks, 256>>>(h, hq8, hn, ha, eix, agg2, E);
    k_gemm2_f2<<<(N + 127) / 128, 256>>>(agg2, W2, b2, out, N);
}

// round 16
// speedup vs baseline: 1.0464x; 1.0464x over previous
#include <cuda_runtime.h>
#include <cuda_bf16.h>
#include <stdint.h>
#include <math.h>

#define EPSF 1e-8f
#define NMAX 50000
#define D1 128
#define D2 256

typedef unsigned long long u64;

// ---------------------------------------------------------------------------
// Scratch (device globals — no allocation allowed).
// ---------------------------------------------------------------------------
__device__ float4 g_agg1_[(size_t)NMAX * D1 / 4];
__device__ float4 g_h_[(size_t)NMAX * D2 / 4];
__device__ float4 g_agg2_[(size_t)NMAX * D2 / 4];
__device__ uint4  g_xq_[(size_t)NMAX * D1 / 16];   // int8 x/||x|| * 127
__device__ uint4  g_hq_[(size_t)NMAX * D2 / 16];   // int8 h/||h|| * 127
__device__ float  g_xnorm[NMAX];
__device__ float  g_hnorm[NMAX];
__device__ float  g_xa[NMAX];                      // sum|q|/127 for x
__device__ float  g_ha[NMAX];                      // sum|q|/127 for h
__device__ int    g_is64;

// ---------------------------------------------------------------------------
// helpers
// ---------------------------------------------------------------------------
__device__ __forceinline__ int dp4a(int a, int b, int c) {
    int d;
    asm("dp4a.s32.s32 %0, %1, %2, %3;" : "=r"(d) : "r"(a), "r"(b), "r"(c));
    return d;
}
__device__ __forceinline__ unsigned q4pack(float4 v, float s127, int& asum) {
    int a0 = __float2int_rn(v.x * s127);
    int a1 = __float2int_rn(v.y * s127);
    int a2 = __float2int_rn(v.z * s127);
    int a3 = __float2int_rn(v.w * s127);
    asum += abs(a0) + abs(a1) + abs(a2) + abs(a3);
    return (unsigned)(a0 & 0xFF) | ((unsigned)(a1 & 0xFF) << 8) |
           ((unsigned)(a2 & 0xFF) << 16) | ((unsigned)(a3 & 0xFF) << 24);
}
// packed f32x2 FMA (B300 FFMA2)
__device__ __forceinline__ u64 dup2(float a) {
    u64 r;
    asm("mov.b64 %0, {%1, %1};" : "=l"(r) : "f"(a));
    return r;
}
__device__ __forceinline__ u64 fma2(u64 a, u64 b, u64 c) {
    u64 d;
    asm("fma.rn.f32x2 %0, %1, %2, %3;" : "=l"(d) : "l"(a), "l"(b), "l"(c));
    return d;
}
__device__ __forceinline__ float2 unpk(u64 a) {
    float2 f;
    asm("mov.b64 {%0, %1}, %2;" : "=f"(f.x), "=f"(f.y) : "l"(a));
    return f;
}

// ---------------------------------------------------------------------------
// setup kernels
// ---------------------------------------------------------------------------
__global__ void k_reset_flag() { g_is64 = 1; }

__global__ void k_detect64(const void* __restrict__ eidx, int E, int N) {
    int i = blockIdx.x * blockDim.x + threadIdx.x;
    if (i < E) {
        long long v = ((const long long*)eidx)[i];
        if (v < 0 || v >= (long long)N) g_is64 = 0;
    }
}

// ---------------------------------------------------------------------------
// Per-node norms + self-loop init + int8 quantization of x/||x|| (layer 1).
// ---------------------------------------------------------------------------
__global__ void k_norms_init128(const float* __restrict__ feat,
                                float* __restrict__ norms,
                                float* __restrict__ absums,
                                float* __restrict__ agg,
                                unsigned* __restrict__ fq, int N)
{
    int node = (blockIdx.x * blockDim.x + threadIdx.x) >> 5;
    int lane = threadIdx.x & 31;
    if (node >= N) return;
    const float4* f = (const float4*)(feat + (size_t)node * D1);
    float4* a = (float4*)(agg + (size_t)node * D1);
    float4 v = f[lane];
    float n2 = v.x * v.x + v.y * v.y + v.z * v.z + v.w * v.w;
#pragma unroll
    for (int o = 16; o; o >>= 1) n2 += __shfl_xor_sync(0xffffffffu, n2, o);
    float nrm = sqrtf(n2);
    if (lane == 0) norms[node] = nrm;
    float s127 = (nrm > 0.f) ? 127.f / nrm : 0.f;
    int asum = 0;
    fq[(size_t)node * 32 + lane] = q4pack(v, s127, asum);
#pragma unroll
    for (int o = 16; o; o >>= 1) asum += __shfl_xor_sync(0xffffffffu, asum, o);
    if (lane == 0) absums[node] = (float)asum * (1.f / 127.f);
    float denom = fmaxf(nrm * nrm, EPSF);
    bool pass = n2 > 0.5f * denom;
    float4 z = make_float4(0.f, 0.f, 0.f, 0.f);
    a[lane] = pass ? v : z;
}

// ---------------------------------------------------------------------------
// Edge pass: 8 lanes/edge, 2 edges per group (8 edges/warp), int8 DP4A.
// All loads for both edges front-batched -> 2x MLP on the latency chain.
// ---------------------------------------------------------------------------
template<int D>
__global__ void k_edge_i8(const float* __restrict__ feat,
                          const uint4* __restrict__ fq,
                          const float* __restrict__ norms,
                          const float* __restrict__ absums,
                          const void* __restrict__ eidx,
                          float* __restrict__ agg, int E)
{
    constexpr int NSTRIDE = D / 16;   // uint4 per int8 row
    constexpr int NU = D / 128;       // uint4 per lane per endpoint
    long long wid = (long long)((blockIdx.x * (unsigned)blockDim.x + threadIdx.x) >> 5);
    long long base = wid * 8;
    if (base >= E) return;
    int lane = threadIdx.x & 31;
    int sl = lane & 7;
    int grp = lane >> 3;

    long long e0 = base + grp;        // edges base..base+3
    long long e1 = base + 4 + grp;    // edges base+4..base+7
    bool v0 = (e0 < E), v1 = (e1 < E);
    long long c0 = v0 ? e0 : (long long)E - 1;
    long long c1 = v1 ? e1 : (long long)E - 1;

    int s0, d0, s1, d1;
    if (g_is64) {
        const long long* p = (const long long*)eidx;
        s0 = (int)p[c0]; d0 = (int)p[c0 + E];
        s1 = (int)p[c1]; d1 = (int)p[c1 + E];
    } else {
        const int* p = (const int*)eidx;
        s0 = p[c0]; d0 = p[c0 + E];
        s1 = p[c1]; d1 = p[c1 + E];
    }
    float SA0 = absums[s0], SB0 = absums[d0];
    float SA1 = absums[s1], SB1 = absums[d1];

    // front-batched feature loads for both edges
    uint4 a0[NU], b0[NU], a1[NU], b1[NU];
    {
        const uint4* ps0 = fq + (size_t)s0 * NSTRIDE;
        const uint4* pd0 = fq + (size_t)d0 * NSTRIDE;
        const uint4* ps1 = fq + (size_t)s1 * NSTRIDE;
        const uint4* pd1 = fq + (size_t)d1 * NSTRIDE;
#pragma unroll
        for (int i = 0; i < NU; i++) {
            a0[i] = ps0[sl + 8 * i];
            b0[i] = pd0[sl + 8 * i];
            a1[i] = ps1[sl + 8 * i];
            b1[i] = pd1[sl + 8 * i];
        }
    }

    int dot0 = 0, dot1 = 0;
#pragma unroll
    for (int i = 0; i < NU; i++) {
        dot0 = dp4a((int)a0[i].x, (int)b0[i].x, dot0);
        dot1 = dp4a((int)a1[i].x, (int)b1[i].x, dot1);
        dot0 = dp4a((int)a0[i].y, (int)b0[i].y, dot0);
        dot1 = dp4a((int)a1[i].y, (int)b1[i].y, dot1);
        dot0 = dp4a((int)a0[i].z, (int)b0[i].z, dot0);
        dot1 = dp4a((int)a1[i].z, (int)b1[i].z, dot1);
        dot0 = dp4a((int)a0[i].w, (int)b0[i].w, dot0);
        dot1 = dp4a((int)a1[i].w, (int)b1[i].w, dot1);
    }
#pragma unroll
    for (int o = 1; o < 8; o <<= 1) {
        dot0 += __shfl_xor_sync(0xffffffffu, dot0, o);
        dot1 += __shfl_xor_sync(0xffffffffu, dot1, o);
    }

    unsigned hm = 0xFFu << (lane & 24);

#pragma unroll
    for (int k = 0; k < 2; k++) {
        int s = k ? s1 : s0;
        int d = k ? d1 : d0;
        bool valid = k ? v1 : v0;
        float t = (float)(k ? dot1 : dot0) * (1.f / 16129.f);
        float margin = ((k ? SA1 : SA0) + (k ? SB1 : SB0) +
                        (float)D * (1.f / 254.f)) * (1.f / 254.f) + 1e-4f;
        bool pass;
        if (fabsf(t - 0.5f) > margin) {
            pass = (t > 0.5f);
        } else {
            // rescue: exact fp32 reference comparison (rare; group-uniform)
            float nn = norms[s] * norms[d];
            const float4* fs = (const float4*)(feat + (size_t)s * D);
            const float4* fd = (const float4*)(feat + (size_t)d * D);
            float ex = 0.f;
#pragma unroll
            for (int i = 0; i < D / 32; i++) {
                float4 av = fs[sl + 8 * i];
                float4 bv = fd[sl + 8 * i];
                ex += av.x * bv.x + av.y * bv.y + av.z * bv.z + av.w * bv.w;
            }
#pragma unroll
            for (int o = 1; o < 8; o <<= 1) ex += __shfl_xor_sync(hm, ex, o);
            pass = (ex > 0.5f * fmaxf(nn, EPSF));
        }

        if (valid && pass) {
            const float4* fs = (const float4*)(feat + (size_t)s * D);
            float* out = agg + (size_t)d * D;
#pragma unroll
            for (int i = 0; i < D / 32; i++) {
                float4 av = fs[sl + 8 * i];
                asm volatile("red.global.add.v4.f32 [%0], {%1,%2,%3,%4};" ::
                             "l"(out + (sl + 8 * i) * 4),
                             "f"(av.x), "f"(av.y), "f"(av.z), "f"(av.w)
                             : "memory");
            }
        }
    }
}

// ---------------------------------------------------------------------------
// GEMM1 (f32x2 + prefetch): h = relu(agg1 @ W1^T + b1). Block 64x256, K=128.
// Fused epilogue: h (fp32), h int8 (normalized), hnorm, h absum, agg2 init.
// ---------------------------------------------------------------------------
__global__ __launch_bounds__(256)
void k_gemm1_f2(const float* __restrict__ A, const float* __restrict__ W,
                const float* __restrict__ bias,
                float* __restrict__ hq, unsigned short* __restrict__ hqi,
                float* __restrict__ hnq, float* __restrict__ haq,
                float* __restrict__ aggq, int M)
{
    __shared__ float As[16][64];
    __shared__ float Ws[16][256];
    int tid = threadIdx.x;
    int tx = tid & 31;
    int ty = tid >> 5;
    int m0 = blockIdx.x * 64;

    int lm = tid >> 2, lkq = tid & 3;
    int lgm = m0 + lm;
    if (lgm >= M) lgm = M - 1;
    const float* Arow = A + (size_t)lgm * 128 + lkq * 4;
    const float* Wbase = W + (size_t)lm * 128 + lkq * 4;

    u64 acc[8][4];
#pragma unroll
    for (int i = 0; i < 8; i++)
#pragma unroll
        for (int j = 0; j < 4; j++) acc[i][j] = 0ull;

    float4 va = *(const float4*)Arow;
    float4 vw[4];
#pragma unroll
    for (int j = 0; j < 4; j++)
        vw[j] = *(const float4*)(Wbase + (size_t)j * 64 * 128);

    for (int k0 = 0; k0 < 128; k0 += 16) {
        As[lkq * 4 + 0][lm] = va.x;
        As[lkq * 4 + 1][lm] = va.y;
        As[lkq * 4 + 2][lm] = va.z;
        As[lkq * 4 + 3][lm] = va.w;
#pragma unroll
        for (int j = 0; j < 4; j++) {
            int n = lm + 64 * j;
            Ws[lkq * 4 + 0][n] = vw[j].x;
            Ws[lkq * 4 + 1][n] = vw[j].y;
            Ws[lkq * 4 + 2][n] = vw[j].z;
            Ws[lkq * 4 + 3][n] = vw[j].w;
        }
        __syncthreads();
        if (k0 + 16 < 128) {
            va = *(const float4*)(Arow + k0 + 16);
#pragma unroll
            for (int j = 0; j < 4; j++)
                vw[j] = *(const float4*)(Wbase + (size_t)j * 64 * 128 + k0 + 16);
        }
#pragma unroll
        for (int k = 0; k < 16; k++) {
            u64 rm2[8], rn[4];
#pragma unroll
            for (int i = 0; i < 8; i++) rm2[i] = dup2(As[k][ty * 8 + i]);
#pragma unroll
            for (int j = 0; j < 4; j++)
                rn[j] = *(const u64*)&Ws[k][2 * tx + 64 * j];
#pragma unroll
            for (int i = 0; i < 8; i++)
#pragma unroll
                for (int j = 0; j < 4; j++)
                    acc[i][j] = fma2(rm2[i], rn[j], acc[i][j]);
        }
        __syncthreads();
    }

    float2 bb[4];
#pragma unroll
    for (int j = 0; j < 4; j++) bb[j] = *(const float2*)&bias[2 * tx + 64 * j];

#pragma unroll
    for (int i = 0; i < 8; i++) {
        int gm = m0 + ty * 8 + i;
        float v[8];
        float n2 = 0.f;
#pragma unroll
        for (int j = 0; j < 4; j++) {
            float2 t = unpk(acc[i][j]);
            float v0 = fmaxf(t.x + bb[j].x, 0.f);
            float v1 = fmaxf(t.y + bb[j].y, 0.f);
            v[2 * j] = v0;
            v[2 * j + 1] = v1;
            n2 += v0 * v0 + v1 * v1;
        }
#pragma unroll
        for (int o = 16; o; o >>= 1) n2 += __shfl_xor_sync(0xffffffffu, n2, o);
        bool pass = n2 > 0.5f * fmaxf(n2, EPSF);
        float nrm = sqrtf(n2);
        float s127 = (nrm > 0.f) ? 127.f / nrm : 0.f;
        int asum = 0;
        unsigned short qp[4];
#pragma unroll
        for (int j = 0; j < 4; j++) {
            int q0 = __float2int_rn(v[2 * j] * s127);
            int q1 = __float2int_rn(v[2 * j + 1] * s127);
            asum += q0 + q1;   // relu'd -> nonnegative
            qp[j] = (unsigned short)((q0 & 0xFF) | ((q1 & 0xFF) << 8));
        }
#pragma unroll
        for (int o = 16; o; o >>= 1) asum += __shfl_xor_sync(0xffffffffu, asum, o);
        if (gm < M) {
            if (tx == 0) {
                hnq[gm] = nrm;
                haq[gm] = (float)asum * (1.f / 127.f);
            }
            float2 z2 = make_float2(0.f, 0.f);
#pragma unroll
            for (int j = 0; j < 4; j++) {
                float2 hv = make_float2(v[2 * j], v[2 * j + 1]);
                *(float2*)(hq + (size_t)gm * 256 + 2 * tx + 64 * j) = hv;
                *(float2*)(aggq + (size_t)gm * 256 + 2 * tx + 64 * j) = pass ? hv : z2;
                hqi[(size_t)gm * 128 + tx + 32 * j] = qp[j];
            }
        }
    }
}

// ---------------------------------------------------------------------------
// GEMM2 (f32x2 + prefetch): out = log_softmax(agg2 @ W2^T + b2). 128x64, K=256.
// ---------------------------------------------------------------------------
__global__ __launch_bounds__(256)
void k_gemm2_f2(const float* __restrict__ A, const float* __restrict__ W,
                const float* __restrict__ bias,
                float* __restrict__ outq, int M)
{
    __shared__ float As[16][128];
    __shared__ float Ws[16][64];
    int tid = threadIdx.x;
    int tx = tid & 15;
    int ty = tid >> 4;
    int m0 = blockIdx.x * 128;

    int lm = tid >> 2, lkq = tid & 3;
    int lgm0 = m0 + lm;
    if (lgm0 >= M) lgm0 = M - 1;
    int lgm1 = m0 + lm + 64;
    if (lgm1 >= M) lgm1 = M - 1;
    const float* Arow0 = A + (size_t)lgm0 * 256 + lkq * 4;
    const float* Arow1 = A + (size_t)lgm1 * 256 + lkq * 4;
    const float* Wrow = W + (size_t)lm * 256 + lkq * 4;

    u64 acc[8][2];
#pragma unroll
    for (int i = 0; i < 8; i++) {
        acc[i][0] = 0ull;
        acc[i][1] = 0ull;
    }

    float4 va0 = *(const float4*)Arow0;
    float4 va1 = *(const float4*)Arow1;
    float4 vw = *(const float4*)Wrow;

    for (int k0 = 0; k0 < 256; k0 += 16) {
        As[lkq * 4 + 0][lm] = va0.x;
        As[lkq * 4 + 1][lm] = va0.y;
        As[lkq * 4 + 2][lm] = va0.z;
        As[lkq * 4 + 3][lm] = va0.w;
        As[lkq * 4 + 0][lm + 64] = va1.x;
        As[lkq * 4 + 1][lm + 64] = va1.y;
        As[lkq * 4 + 2][lm + 64] = va1.z;
        As[lkq * 4 + 3][lm + 64] = va1.w;
        Ws[lkq * 4 + 0][lm] = vw.x;
        Ws[lkq * 4 + 1][lm] = vw.y;
        Ws[lkq * 4 + 2][lm] = vw.z;
        Ws[lkq * 4 + 3][lm] = vw.w;
        __syncthreads();
        if (k0 + 16 < 256) {
            va0 = *(const float4*)(Arow0 + k0 + 16);
            va1 = *(const float4*)(Arow1 + k0 + 16);
            vw = *(const float4*)(Wrow + k0 + 16);
        }
#pragma unroll
        for (int k = 0; k < 16; k++) {
            u64 rm2[8], rn[2];
#pragma unroll
            for (int i = 0; i < 8; i++) rm2[i] = dup2(As[k][ty * 8 + i]);
            rn[0] = *(const u64*)&Ws[k][2 * tx];
            rn[1] = *(const u64*)&Ws[k][2 * tx + 32];
#pragma unroll
            for (int i = 0; i < 8; i++) {
                acc[i][0] = fma2(rm2[i], rn[0], acc[i][0]);
                acc[i][1] = fma2(rm2[i], rn[1], acc[i][1]);
            }
        }
        __syncthreads();
    }

    float2 bb0 = *(const float2*)&bias[2 * tx];
    float2 bb1 = *(const float2*)&bias[2 * tx + 32];

#pragma unroll
    for (int i = 0; i < 8; i++) {
        int gm = m0 + ty * 8 + i;
        float2 t0 = unpk(acc[i][0]);
        float2 t1 = unpk(acc[i][1]);
        float v0 = t0.x + bb0.x, v1 = t0.y + bb0.y;
        float v2 = t1.x + bb1.x, v3 = t1.y + bb1.y;
        float mx = fmaxf(fmaxf(v0, v1), fmaxf(v2, v3));
#pragma unroll
        for (int o = 1; o < 16; o <<= 1)
            mx = fmaxf(mx, __shfl_xor_sync(0xffffffffu, mx, o));
        float sm = __expf(v0 - mx) + __expf(v1 - mx) +
                   __expf(v2 - mx) + __expf(v3 - mx);
#pragma unroll
        for (int o = 1; o < 16; o <<= 1)
            sm += __shfl_xor_sync(0xffffffffu, sm, o);
        float l = mx + __logf(sm);
        if (gm < M) {
            *(float2*)(outq + (size_t)gm * 64 + 2 * tx) = make_float2(v0 - l, v1 - l);
            *(float2*)(outq + (size_t)gm * 64 + 2 * tx + 32) = make_float2(v2 - l, v3 - l);
        }
    }
}

// ---------------------------------------------------------------------------
extern "C" void kernel_launch(void* const* d_in, const int* in_sizes, int n_in,
                              void* d_out, int out_size)
{
    const float* x   = (const float*)d_in[0];
    const void*  eix = d_in[1];
    const float* W1  = (const float*)d_in[2];
    const float* b1  = (const float*)d_in[3];
    const float* W2  = (const float*)d_in[4];
    const float* b2  = (const float*)d_in[5];
    float* out = (float*)d_out;

    int N = in_sizes[0] / D1;      // 50000
    int E = in_sizes[1] / 2;       // 800000
    (void)n_in; (void)out_size;

    float *agg1, *h, *agg2, *xn, *hn, *xa, *ha;
    uint4 *xq, *hq8;
    cudaGetSymbolAddress((void**)&agg1, g_agg1_);
    cudaGetSymbolAddress((void**)&h,    g_h_);
    cudaGetSymbolAddress((void**)&agg2, g_agg2_);
    cudaGetSymbolAddress((void**)&xq,   g_xq_);
    cudaGetSymbolAddress((void**)&hq8,  g_hq_);
    cudaGetSymbolAddress((void**)&xn,   g_xnorm);
    cudaGetSymbolAddress((void**)&hn,   g_hnorm);
    cudaGetSymbolAddress((void**)&xa,   g_xa);
    cudaGetSymbolAddress((void**)&ha,   g_ha);

    k_reset_flag<<<1, 1>>>();
    k_detect64<<<(E + 255) / 256, 256>>>(eix, E, N);

    int nodeBlocks = (N * 32 + 255) / 256;
    long long warps8 = ((long long)E + 7) / 8;
    int edgeBlocks = (int)((warps8 * 32 + 255) / 256);

    // ---- Layer 1 ----
    k_norms_init128<<<nodeBlocks, 256>>>(x, xn, xa, agg1, (unsigned*)xq, N);
    k_edge_i8<D1><<<edgeBlocks, 256>>>(x, xq, xn, xa, eix, agg1, E);
    k_gemm1_f2<<<(N + 63) / 64, 256>>>(agg1, W1, b1, h, (unsigned short*)hq8, hn, ha, agg2, N);

    // ---- Layer 2 ----
    k_edge_i8<D2><<<edgeBlocks, 256>>>(h, hq8, hn, ha, eix, agg2, E);
    k_gemm2_f2<<<(N + 127) / 128, 256>>>(agg2, W2, b2, out, N);
}

// round 17
// speedup vs baseline: 1.0827x; 1.0348x over previous
#include <cuda_runtime.h>
#include <cuda_bf16.h>
#include <stdint.h>
#include <math.h>

#define EPSF 1e-8f
#define NMAX 50000
#define D1 128
#define D2 256
#define BF16_MARGIN 0.02f

typedef unsigned long long u64;

// ---------------------------------------------------------------------------
// Scratch (device globals — no allocation allowed).
// ---------------------------------------------------------------------------
__device__ float4 g_agg1_[(size_t)NMAX * D1 / 4];
__device__ float4 g_h_[(size_t)NMAX * D2 / 4];
__device__ float4 g_agg2_[(size_t)NMAX * D2 / 4];
__device__ uint4  g_xq_[(size_t)NMAX * D1 / 16];   // int8 x/||x|| * 127
__device__ uint4  g_hb_[(size_t)NMAX * D2 / 8];    // bf16 h/||h||
__device__ float  g_xnorm[NMAX];
__device__ float  g_hnorm[NMAX];
__device__ float  g_xa[NMAX];                      // sum|q|/127 for x
__device__ int    g_is64;

// ---------------------------------------------------------------------------
// helpers
// ---------------------------------------------------------------------------
__device__ __forceinline__ int dp4a(int a, int b, int c) {
    int d;
    asm("dp4a.s32.s32 %0, %1, %2, %3;" : "=r"(d) : "r"(a), "r"(b), "r"(c));
    return d;
}
__device__ __forceinline__ unsigned q4pack(float4 v, float s127, int& asum) {
    int a0 = __float2int_rn(v.x * s127);
    int a1 = __float2int_rn(v.y * s127);
    int a2 = __float2int_rn(v.z * s127);
    int a3 = __float2int_rn(v.w * s127);
    asum += abs(a0) + abs(a1) + abs(a2) + abs(a3);
    return (unsigned)(a0 & 0xFF) | ((unsigned)(a1 & 0xFF) << 8) |
           ((unsigned)(a2 & 0xFF) << 16) | ((unsigned)(a3 & 0xFF) << 24);
}
__device__ __forceinline__ unsigned pack2bf(float a, float b) {
    __nv_bfloat162 t = __floats2bfloat162_rn(a, b);
    return *(unsigned*)&t;
}
// bf16 dot of one uint4 pair (8 bf16 lanes), returned as float
__device__ __forceinline__ float bfdot_u4(uint4 a, uint4 b) {
    __nv_bfloat162 acc = __float2bfloat162_rn(0.f);
    const __nv_bfloat162* pa = (const __nv_bfloat162*)&a;
    const __nv_bfloat162* pb = (const __nv_bfloat162*)&b;
#pragma unroll
    for (int j = 0; j < 4; j++) acc = __hfma2(pa[j], pb[j], acc);
    float2 f = __bfloat1622float2(acc);
    return f.x + f.y;
}
// packed f32x2 FMA (B300 FFMA2)
__device__ __forceinline__ u64 dup2(float a) {
    u64 r;
    asm("mov.b64 %0, {%1, %1};" : "=l"(r) : "f"(a));
    return r;
}
__device__ __forceinline__ u64 fma2(u64 a, u64 b, u64 c) {
    u64 d;
    asm("fma.rn.f32x2 %0, %1, %2, %3;" : "=l"(d) : "l"(a), "l"(b), "l"(c));
    return d;
}
__device__ __forceinline__ float2 unpk(u64 a) {
    float2 f;
    asm("mov.b64 {%0, %1}, %2;" : "=f"(f.x), "=f"(f.y) : "l"(a));
    return f;
}

// ---------------------------------------------------------------------------
// setup kernels
// ---------------------------------------------------------------------------
__global__ void k_reset_flag() { g_is64 = 1; }

__global__ void k_detect64(const void* __restrict__ eidx, int E, int N) {
    int i = blockIdx.x * blockDim.x + threadIdx.x;
    if (i < E) {
        long long v = ((const long long*)eidx)[i];
        if (v < 0 || v >= (long long)N) g_is64 = 0;
    }
}

// ---------------------------------------------------------------------------
// Per-node norms + self-loop init + int8 quantization of x/||x|| (layer 1).
// ---------------------------------------------------------------------------
__global__ void k_norms_init128(const float* __restrict__ feat,
                                float* __restrict__ norms,
                                float* __restrict__ absums,
                                float* __restrict__ agg,
                                unsigned* __restrict__ fq, int N)
{
    int node = (blockIdx.x * blockDim.x + threadIdx.x) >> 5;
    int lane = threadIdx.x & 31;
    if (node >= N) return;
    const float4* f = (const float4*)(feat + (size_t)node * D1);
    float4* a = (float4*)(agg + (size_t)node * D1);
    float4 v = f[lane];
    float n2 = v.x * v.x + v.y * v.y + v.z * v.z + v.w * v.w;
#pragma unroll
    for (int o = 16; o; o >>= 1) n2 += __shfl_xor_sync(0xffffffffu, n2, o);
    float nrm = sqrtf(n2);
    if (lane == 0) norms[node] = nrm;
    float s127 = (nrm > 0.f) ? 127.f / nrm : 0.f;
    int asum = 0;
    fq[(size_t)node * 32 + lane] = q4pack(v, s127, asum);
#pragma unroll
    for (int o = 16; o; o >>= 1) asum += __shfl_xor_sync(0xffffffffu, asum, o);
    if (lane == 0) absums[node] = (float)asum * (1.f / 127.f);
    float denom = fmaxf(nrm * nrm, EPSF);
    bool pass = n2 > 0.5f * denom;
    float4 z = make_float4(0.f, 0.f, 0.f, 0.f);
    a[lane] = pass ? v : z;
}

// ---------------------------------------------------------------------------
// Layer-1 edge pass: 8 lanes/edge, 2 edges per group (8 edges/warp), int8 DP4A.
// (R16, proven.)
// ---------------------------------------------------------------------------
__global__ void k_edge128_i8(const float* __restrict__ feat,
                             const uint4* __restrict__ fq,
                             const float* __restrict__ norms,
                             const float* __restrict__ absums,
                             const void* __restrict__ eidx,
                             float* __restrict__ agg, int E)
{
    long long wid = (long long)((blockIdx.x * (unsigned)blockDim.x + threadIdx.x) >> 5);
    long long base = wid * 8;
    if (base >= E) return;
    int lane = threadIdx.x & 31;
    int sl = lane & 7;
    int grp = lane >> 3;

    long long e0 = base + grp;
    long long e1 = base + 4 + grp;
    bool v0 = (e0 < E), v1 = (e1 < E);
    long long c0 = v0 ? e0 : (long long)E - 1;
    long long c1 = v1 ? e1 : (long long)E - 1;

    int s0, d0, s1, d1;
    if (g_is64) {
        const long long* p = (const long long*)eidx;
        s0 = (int)p[c0]; d0 = (int)p[c0 + E];
        s1 = (int)p[c1]; d1 = (int)p[c1 + E];
    } else {
        const int* p = (const int*)eidx;
        s0 = p[c0]; d0 = p[c0 + E];
        s1 = p[c1]; d1 = p[c1 + E];
    }
    float SA0 = absums[s0], SB0 = absums[d0];
    float SA1 = absums[s1], SB1 = absums[d1];

    uint4 a0, b0, a1, b1;
    a0 = (fq + (size_t)s0 * 8)[sl];
    b0 = (fq + (size_t)d0 * 8)[sl];
    a1 = (fq + (size_t)s1 * 8)[sl];
    b1 = (fq + (size_t)d1 * 8)[sl];

    int dot0 = 0, dot1 = 0;
    dot0 = dp4a((int)a0.x, (int)b0.x, dot0);
    dot1 = dp4a((int)a1.x, (int)b1.x, dot1);
    dot0 = dp4a((int)a0.y, (int)b0.y, dot0);
    dot1 = dp4a((int)a1.y, (int)b1.y, dot1);
    dot0 = dp4a((int)a0.z, (int)b0.z, dot0);
    dot1 = dp4a((int)a1.z, (int)b1.z, dot1);
    dot0 = dp4a((int)a0.w, (int)b0.w, dot0);
    dot1 = dp4a((int)a1.w, (int)b1.w, dot1);
#pragma unroll
    for (int o = 1; o < 8; o <<= 1) {
        dot0 += __shfl_xor_sync(0xffffffffu, dot0, o);
        dot1 += __shfl_xor_sync(0xffffffffu, dot1, o);
    }

    unsigned hm = 0xFFu << (lane & 24);

#pragma unroll
    for (int k = 0; k < 2; k++) {
        int s = k ? s1 : s0;
        int d = k ? d1 : d0;
        bool valid = k ? v1 : v0;
        float t = (float)(k ? dot1 : dot0) * (1.f / 16129.f);
        float margin = ((k ? SA1 : SA0) + (k ? SB1 : SB0) +
                        (float)D1 * (1.f / 254.f)) * (1.f / 254.f) + 1e-4f;
        bool pass;
        if (fabsf(t - 0.5f) > margin) {
            pass = (t > 0.5f);
        } else {
            float nn = norms[s] * norms[d];
            const float4* fs = (const float4*)(feat + (size_t)s * D1);
            const float4* fd = (const float4*)(feat + (size_t)d * D1);
            float ex = 0.f;
#pragma unroll
            for (int i = 0; i < 4; i++) {
                float4 av = fs[sl + 8 * i];
                float4 bv = fd[sl + 8 * i];
                ex += av.x * bv.x + av.y * bv.y + av.z * bv.z + av.w * bv.w;
            }
#pragma unroll
            for (int o = 1; o < 8; o <<= 1) ex += __shfl_xor_sync(hm, ex, o);
            pass = (ex > 0.5f * fmaxf(nn, EPSF));
        }

        if (valid && pass) {
            const float4* fs = (const float4*)(feat + (size_t)s * D1);
            float* out = agg + (size_t)d * D1;
#pragma unroll
            for (int i = 0; i < 4; i++) {
                float4 av = fs[sl + 8 * i];
                asm volatile("red.global.add.v4.f32 [%0], {%1,%2,%3,%4};" ::
                             "l"(out + (sl + 8 * i) * 4),
                             "f"(av.x), "f"(av.y), "f"(av.z), "f"(av.w)
                             : "memory");
            }
        }
    }
}

// ---------------------------------------------------------------------------
// Layer-2 edge pass: 16 lanes/edge, 2 edges per group (4 edges/warp),
// bf16 normalized features (margin 0.02 -> rescue ~0.1%).
// ---------------------------------------------------------------------------
__global__ void k_edge256_bf(const float* __restrict__ feat,
                             const uint4* __restrict__ fb,
                             const float* __restrict__ norms,
                             const void* __restrict__ eidx,
                             float* __restrict__ agg, int E)
{
    long long wid = (long long)((blockIdx.x * (unsigned)blockDim.x + threadIdx.x) >> 5);
    long long base = wid * 4;
    if (base >= E) return;
    int lane = threadIdx.x & 31;
    int sl = lane & 15;
    int grp = lane >> 4;

    long long e0 = base + grp;
    long long e1 = base + 2 + grp;
    bool v0 = (e0 < E), v1 = (e1 < E);
    long long c0 = v0 ? e0 : (long long)E - 1;
    long long c1 = v1 ? e1 : (long long)E - 1;

    int s0, d0, s1, d1;
    if (g_is64) {
        const long long* p = (const long long*)eidx;
        s0 = (int)p[c0]; d0 = (int)p[c0 + E];
        s1 = (int)p[c1]; d1 = (int)p[c1 + E];
    } else {
        const int* p = (const int*)eidx;
        s0 = p[c0]; d0 = p[c0 + E];
        s1 = p[c1]; d1 = p[c1 + E];
    }

    // front-batched: 8 independent uint4 loads (256 bf16 row = 32 uint4)
    const uint4* ps0 = fb + (size_t)s0 * 32;
    const uint4* pd0 = fb + (size_t)d0 * 32;
    const uint4* ps1 = fb + (size_t)s1 * 32;
    const uint4* pd1 = fb + (size_t)d1 * 32;
    uint4 a00 = ps0[sl], a01 = ps0[sl + 16];
    uint4 b00 = pd0[sl], b01 = pd0[sl + 16];
    uint4 a10 = ps1[sl], a11 = ps1[sl + 16];
    uint4 b10 = pd1[sl], b11 = pd1[sl + 16];

    float dot0 = bfdot_u4(a00, b00) + bfdot_u4(a01, b01);
    float dot1 = bfdot_u4(a10, b10) + bfdot_u4(a11, b11);
#pragma unroll
    for (int o = 1; o < 16; o <<= 1) {
        dot0 += __shfl_xor_sync(0xffffffffu, dot0, o);
        dot1 += __shfl_xor_sync(0xffffffffu, dot1, o);
    }

    unsigned hm = 0xFFFFu << (lane & 16);

#pragma unroll
    for (int k = 0; k < 2; k++) {
        int s = k ? s1 : s0;
        int d = k ? d1 : d0;
        bool valid = k ? v1 : v0;
        float t = k ? dot1 : dot0;
        bool pass;
        if (fabsf(t - 0.5f) > BF16_MARGIN) {
            pass = (t > 0.5f);
        } else {
            float nn = norms[s] * norms[d];
            const float4* fs = (const float4*)(feat + (size_t)s * D2);
            const float4* fd = (const float4*)(feat + (size_t)d * D2);
            float ex = 0.f;
#pragma unroll
            for (int i = 0; i < 4; i++) {
                float4 av = fs[sl + 16 * i];
                float4 bv = fd[sl + 16 * i];
                ex += av.x * bv.x + av.y * bv.y + av.z * bv.z + av.w * bv.w;
            }
#pragma unroll
            for (int o = 1; o < 16; o <<= 1) ex += __shfl_xor_sync(hm, ex, o);
            pass = (ex > 0.5f * fmaxf(nn, EPSF));
        }

        if (valid && pass) {
            const float4* fs = (const float4*)(feat + (size_t)s * D2);
            float* out = agg + (size_t)d * D2;
#pragma unroll
            for (int i = 0; i < 4; i++) {
                float4 av = fs[sl + 16 * i];
                asm volatile("red.global.add.v4.f32 [%0], {%1,%2,%3,%4};" ::
                             "l"(out + (sl + 16 * i) * 4),
                             "f"(av.x), "f"(av.y), "f"(av.z), "f"(av.w)
                             : "memory");
            }
        }
    }
}

// ---------------------------------------------------------------------------
// GEMM1 (f32x2 + prefetch): h = relu(agg1 @ W1^T + b1). Block 64x256, K=128.
// Fused epilogue: h (fp32), hb (normalized bf16), hnorm, agg2 init.
// ---------------------------------------------------------------------------
__global__ __launch_bounds__(256)
void k_gemm1_f2(const float* __restrict__ A, const float* __restrict__ W,
                const float* __restrict__ bias,
                float* __restrict__ hq, unsigned* __restrict__ hbq,
                float* __restrict__ hnq, float* __restrict__ aggq, int M)
{
    __shared__ float As[16][64];
    __shared__ float Ws[16][256];
    int tid = threadIdx.x;
    int tx = tid & 31;
    int ty = tid >> 5;
    int m0 = blockIdx.x * 64;

    int lm = tid >> 2, lkq = tid & 3;
    int lgm = m0 + lm;
    if (lgm >= M) lgm = M - 1;
    const float* Arow = A + (size_t)lgm * 128 + lkq * 4;
    const float* Wbase = W + (size_t)lm * 128 + lkq * 4;

    u64 acc[8][4];
#pragma unroll
    for (int i = 0; i < 8; i++)
#pragma unroll
        for (int j = 0; j < 4; j++) acc[i][j] = 0ull;

    float4 va = *(const float4*)Arow;
    float4 vw[4];
#pragma unroll
    for (int j = 0; j < 4; j++)
        vw[j] = *(const float4*)(Wbase + (size_t)j * 64 * 128);

    for (int k0 = 0; k0 < 128; k0 += 16) {
        As[lkq * 4 + 0][lm] = va.x;
        As[lkq * 4 + 1][lm] = va.y;
        As[lkq * 4 + 2][lm] = va.z;
        As[lkq * 4 + 3][lm] = va.w;
#pragma unroll
        for (int j = 0; j < 4; j++) {
            int n = lm + 64 * j;
            Ws[lkq * 4 + 0][n] = vw[j].x;
            Ws[lkq * 4 + 1][n] = vw[j].y;
            Ws[lkq * 4 + 2][n] = vw[j].z;
            Ws[lkq * 4 + 3][n] = vw[j].w;
        }
        __syncthreads();
        if (k0 + 16 < 128) {
            va = *(const float4*)(Arow + k0 + 16);
#pragma unroll
            for (int j = 0; j < 4; j++)
                vw[j] = *(const float4*)(Wbase + (size_t)j * 64 * 128 + k0 + 16);
        }
#pragma unroll
        for (int k = 0; k < 16; k++) {
            u64 rm2[8], rn[4];
#pragma unroll
            for (int i = 0; i < 8; i++) rm2[i] = dup2(As[k][ty * 8 + i]);
#pragma unroll
            for (int j = 0; j < 4; j++)
                rn[j] = *(const u64*)&Ws[k][2 * tx + 64 * j];
#pragma unroll
            for (int i = 0; i < 8; i++)
#pragma unroll
                for (int j = 0; j < 4; j++)
                    acc[i][j] = fma2(rm2[i], rn[j], acc[i][j]);
        }
        __syncthreads();
    }

    float2 bb[4];
#pragma unroll
    for (int j = 0; j < 4; j++) bb[j] = *(const float2*)&bias[2 * tx + 64 * j];

#pragma unroll
    for (int i = 0; i < 8; i++) {
        int gm = m0 + ty * 8 + i;
        float v[8];
        float n2 = 0.f;
#pragma unroll
        for (int j = 0; j < 4; j++) {
            float2 t = unpk(acc[i][j]);
            float v0 = fmaxf(t.x + bb[j].x, 0.f);
            float v1 = fmaxf(t.y + bb[j].y, 0.f);
            v[2 * j] = v0;
            v[2 * j + 1] = v1;
            n2 += v0 * v0 + v1 * v1;
        }
#pragma unroll
        for (int o = 16; o; o >>= 1) n2 += __shfl_xor_sync(0xffffffffu, n2, o);
        bool pass = n2 > 0.5f * fmaxf(n2, EPSF);
        if (gm < M) {
            float nrm = sqrtf(n2);
            float sc = (nrm > 0.f) ? 1.f / nrm : 0.f;
            if (tx == 0) hnq[gm] = nrm;
            float2 z2 = make_float2(0.f, 0.f);
#pragma unroll
            for (int j = 0; j < 4; j++) {
                float2 hv = make_float2(v[2 * j], v[2 * j + 1]);
                *(float2*)(hq + (size_t)gm * 256 + 2 * tx + 64 * j) = hv;
                *(float2*)(aggq + (size_t)gm * 256 + 2 * tx + 64 * j) = pass ? hv : z2;
                hbq[(size_t)gm * 128 + tx + 32 * j] = pack2bf(hv.x * sc, hv.y * sc);
            }
        }
    }
}

// ---------------------------------------------------------------------------
// GEMM2 (f32x2 + prefetch): out = log_softmax(agg2 @ W2^T + b2). 128x64, K=256.
// ---------------------------------------------------------------------------
__global__ __launch_bounds__(256)
void k_gemm2_f2(const float* __restrict__ A, const float* __restrict__ W,
                const float* __restrict__ bias,
                float* __restrict__ outq, int M)
{
    __shared__ float As[16][128];
    __shared__ float Ws[16][64];
    int tid = threadIdx.x;
    int tx = tid & 15;
    int ty = tid >> 4;
    int m0 = blockIdx.x * 128;

    int lm = tid >> 2, lkq = tid & 3;
    int lgm0 = m0 + lm;
    if (lgm0 >= M) lgm0 = M - 1;
    int lgm1 = m0 + lm + 64;
    if (lgm1 >= M) lgm1 = M - 1;
    const float* Arow0 = A + (size_t)lgm0 * 256 + lkq * 4;
    const float* Arow1 = A + (size_t)lgm1 * 256 + lkq * 4;
    const float* Wrow = W + (size_t)lm * 256 + lkq * 4;

    u64 acc[8][2];
#pragma unroll
    for (int i = 0; i < 8; i++) {
        acc[i][0] = 0ull;
        acc[i][1] = 0ull;
    }

    float4 va0 = *(const float4*)Arow0;
    float4 va1 = *(const float4*)Arow1;
    float4 vw = *(const float4*)Wrow;

    for (int k0 = 0; k0 < 256; k0 += 16) {
        As[lkq * 4 + 0][lm] = va0.x;
        As[lkq * 4 + 1][lm] = va0.y;
        As[lkq * 4 + 2][lm] = va0.z;
        As[lkq * 4 + 3][lm] = va0.w;
        As[lkq * 4 + 0][lm + 64] = va1.x;
        As[lkq * 4 + 1][lm + 64] = va1.y;
        As[lkq * 4 + 2][lm + 64] = va1.z;
        As[lkq * 4 + 3][lm + 64] = va1.w;
        Ws[lkq * 4 + 0][lm] = vw.x;
        Ws[lkq * 4 + 1][lm] = vw.y;
        Ws[lkq * 4 + 2][lm] = vw.z;
        Ws[lkq * 4 + 3][lm] = vw.w;
        __syncthreads();
        if (k0 + 16 < 256) {
            va0 = *(const float4*)(Arow0 + k0 + 16);
            va1 = *(const float4*)(Arow1 + k0 + 16);
            vw = *(const float4*)(Wrow + k0 + 16);
        }
#pragma unroll
        for (int k = 0; k < 16; k++) {
            u64 rm2[8], rn[2];
#pragma unroll
            for (int i = 0; i < 8; i++) rm2[i] = dup2(As[k][ty * 8 + i]);
            rn[0] = *(const u64*)&Ws[k][2 * tx];
            rn[1] = *(const u64*)&Ws[k][2 * tx + 32];
#pragma unroll
            for (int i = 0; i < 8; i++) {
                acc[i][0] = fma2(rm2[i], rn[0], acc[i][0]);
                acc[i][1] = fma2(rm2[i], rn[1], acc[i][1]);
            }
        }
        __syncthreads();
    }

    float2 bb0 = *(const float2*)&bias[2 * tx];
    float2 bb1 = *(const float2*)&bias[2 * tx + 32];

#pragma unroll
    for (int i = 0; i < 8; i++) {
        int gm = m0 + ty * 8 + i;
        float2 t0 = unpk(acc[i][0]);
        float2 t1 = unpk(acc[i][1]);
        float v0 = t0.x + bb0.x, v1 = t0.y + bb0.y;
        float v2 = t1.x + bb1.x, v3 = t1.y + bb1.y;
        float mx = fmaxf(fmaxf(v0, v1), fmaxf(v2, v3));
#pragma unroll
        for (int o = 1; o < 16; o <<= 1)
            mx = fmaxf(mx, __shfl_xor_sync(0xffffffffu, mx, o));
        float sm = __expf(v0 - mx) + __expf(v1 - mx) +
                   __expf(v2 - mx) + __expf(v3 - mx);
#pragma unroll
        for (int o = 1; o < 16; o <<= 1)
            sm += __shfl_xor_sync(0xffffffffu, sm, o);
        float l = mx + __logf(sm);
        if (gm < M) {
            *(float2*)(outq + (size_t)gm * 64 + 2 * tx) = make_float2(v0 - l, v1 - l);
            *(float2*)(outq + (size_t)gm * 64 + 2 * tx + 32) = make_float2(v2 - l, v3 - l);
        }
    }
}

// ---------------------------------------------------------------------------
extern "C" void kernel_launch(void* const* d_in, const int* in_sizes, int n_in,
                              void* d_out, int out_size)
{
    const float* x   = (const float*)d_in[0];
    const void*  eix = d_in[1];
    const float* W1  = (const float*)d_in[2];
    const float* b1  = (const float*)d_in[3];
    const float* W2  = (const float*)d_in[4];
    const float* b2  = (const float*)d_in[5];
    float* out = (float*)d_out;

    int N = in_sizes[0] / D1;      // 50000
    int E = in_sizes[1] / 2;       // 800000
    (void)n_in; (void)out_size;

    float *agg1, *h, *agg2, *xn, *hn, *xa;
    uint4 *xq, *hb;
    cudaGetSymbolAddress((void**)&agg1, g_agg1_);
    cudaGetSymbolAddress((void**)&h,    g_h_);
    cudaGetSymbolAddress((void**)&agg2, g_agg2_);
    cudaGetSymbolAddress((void**)&xq,   g_xq_);
    cudaGetSymbolAddress((void**)&hb,   g_hb_);
    cudaGetSymbolAddress((void**)&xn,   g_xnorm);
    cudaGetSymbolAddress((void**)&hn,   g_hnorm);
    cudaGetSymbolAddress((void**)&xa,   g_xa);

    k_reset_flag<<<1, 1>>>();
    k_detect64<<<(E + 255) / 256, 256>>>(eix, E, N);

    int nodeBlocks = (N * 32 + 255) / 256;

    // ---- Layer 1 (int8 DP4A edges, 8 edges/warp) ----
    k_norms_init128<<<nodeBlocks, 256>>>(x, xn, xa, agg1, (unsigned*)xq, N);
    {
        long long warps = ((long long)E + 7) / 8;
        int blocks = (int)((warps * 32 + 255) / 256);
        k_edge128_i8<<<blocks, 256>>>(x, xq, xn, xa, eix, agg1, E);
    }
    k_gemm1_f2<<<(N + 63) / 64, 256>>>(agg1, W1, b1, h, (unsigned*)hb, hn, agg2, N);

    // ---- Layer 2 (bf16 edges, 16 lanes/edge, 4 edges/warp) ----
    {
        long long warps = ((long long)E + 3) / 4;
        int blocks = (int)((warps * 32 + 255) / 256);
        k_edge256_bf<<<blocks, 256>>>(h, hb, hn, eix, agg2, E);
    }
    k_gemm2_f2<<<(N + 127) / 128, 256>>>(agg2, W2, b2, out, N);
}